// round 7
// baseline (speedup 1.0000x reference)
#include <cuda_runtime.h>
#include <cuda_bf16.h>
#include <mma.h>
#include <cstdint>

using namespace nvcuda;

#define N_VOX 200000
#define PP    65536
#define EPSV  1e-5f

// ---- scratch (__device__ globals; allocation-free rule) ----
__device__ float g_h1[(size_t)N_VOX * 64];
__device__ float g_h2[(size_t)N_VOX * 64];
__device__ __nv_bfloat16 g_wb[27 * 9216];  // [27][hi 64x72 | lo 64x72] bf16, padded
__device__ float g_stats[256];
__device__ float g_coef[256];  // [0:64] scale1 [64:128] shift1 [128:192] scale2 [192:256] shift2

#define RED4(p, a, b, c, d) \
    asm volatile("red.global.add.v4.f32 [%0], {%1,%2,%3,%4};" \
                 :: "l"(p), "f"(a), "f"(b), "f"(c), "f"(d) : "memory")

// smem layout (bytes):
//   [0,     18432)  sAh bf16 [128][72]
//   [18432, 36864)  sAl bf16 [128][72]
//   [36864, 55296)  sW  bf16 [hi 64x72 | lo 64x72]
//   [0,     32768)  sD  f32 [128][64]   (reuses A region after compute; SCATTER only)
//   [55296, 55808)  s_row [128]
//   [55808, 56320)  s_orow[128]
#define DSMEM_BYTES 56320

// ---------------------------------------------------------------------------
template <bool SCATTER, bool FUSE_BN>
__global__ __launch_bounds__(128, 4)
void conv_mma_kernel(const float* __restrict__ x,
                     const __nv_bfloat16* __restrict__ wb,
                     const int* __restrict__ in_map,
                     const int* __restrict__ out_map,
                     float* __restrict__ H)
{
    extern __shared__ char sm[];
    __nv_bfloat16* sAh = reinterpret_cast<__nv_bfloat16*>(sm);
    __nv_bfloat16* sAl = sAh + 128 * 72;
    __nv_bfloat16* sWh = reinterpret_cast<__nv_bfloat16*>(sm + 36864);
    __nv_bfloat16* sWl = sWh + 64 * 72;
    float*         sD  = reinterpret_cast<float*>(sm);
    int*           s_row  = reinterpret_cast<int*>(sm + 55296);
    int*           s_orow = s_row + 128;

    const int t    = threadIdx.x;
    const int w    = t >> 5;
    const int lane = t & 31;
    const int base = blockIdx.x * 128;
    const int ky   = SCATTER ? blockIdx.y : 0;
    const int o    = SCATTER ? (ky < 13 ? ky : ky + 1) : 13;

    if (SCATTER) {
        const size_t kbase = (size_t)ky * PP + base;
        if (__ldg(&in_map[kbase]) >= N_VOX) return;   // sentinel tail-packed tile
        s_row[t]  = __ldg(&in_map[kbase + t]);
        s_orow[t] = __ldg(&out_map[kbase + t]);
    } else {
        s_row[t] = base + t;
    }

    // Stage W_o (hi+lo, padded stride 72, 18432 B flat copy)
    {
        const uint4* src = reinterpret_cast<const uint4*>(wb + (size_t)o * 9216);
        uint4*       dst = reinterpret_cast<uint4*>(sm + 36864);
#pragma unroll
        for (int i = 0; i < 9; i++) dst[t + i * 128] = src[t + i * 128];
    }
    __syncthreads();

    // Gather (+ optional fused BN1+ReLU) + bf16 hi/lo split.
    // 16 lanes cover one row: coalesced 2 rows / 4x128B lines per warp op.
    {
        const int rsub = lane >> 4;
        const int c4   = lane & 15;
        const float4* x4 = reinterpret_cast<const float4*>(x);
        float s0, s1, s2, s3, b0, b1, b2, b3;
        if (FUSE_BN) {
            const int cb = c4 * 4;
            s0 = g_coef[cb + 0]; b0 = g_coef[64 + cb + 0];
            s1 = g_coef[cb + 1]; b1 = g_coef[64 + cb + 1];
            s2 = g_coef[cb + 2]; b2 = g_coef[64 + cb + 2];
            s3 = g_coef[cb + 3]; b3 = g_coef[64 + cb + 3];
        }
#pragma unroll
        for (int j = 0; j < 16; j++) {
            const int r   = w * 32 + j * 2 + rsub;
            const int row = s_row[r];
            float4 v = make_float4(0.f, 0.f, 0.f, 0.f);
            if (row < N_VOX) v = x4[(size_t)row * 16 + c4];
            if (FUSE_BN) {
                v.x = fmaxf(fmaf(v.x, s0, b0), 0.f);
                v.y = fmaxf(fmaf(v.y, s1, b1), 0.f);
                v.z = fmaxf(fmaf(v.z, s2, b2), 0.f);
                v.w = fmaxf(fmaf(v.w, s3, b3), 0.f);
            }
            union { __nv_bfloat16 b[4]; uint2 u; } hi, lo;
            hi.b[0] = __float2bfloat16(v.x);
            hi.b[1] = __float2bfloat16(v.y);
            hi.b[2] = __float2bfloat16(v.z);
            hi.b[3] = __float2bfloat16(v.w);
            lo.b[0] = __float2bfloat16(v.x - __bfloat162float(hi.b[0]));
            lo.b[1] = __float2bfloat16(v.y - __bfloat162float(hi.b[1]));
            lo.b[2] = __float2bfloat16(v.z - __bfloat162float(hi.b[2]));
            lo.b[3] = __float2bfloat16(v.w - __bfloat162float(hi.b[3]));
            *reinterpret_cast<uint2*>(sAh + r * 72 + c4 * 4) = hi.u;
            *reinterpret_cast<uint2*>(sAl + r * 72 + c4 * 4) = lo.u;
        }
    }
    __syncthreads();

    // Warp w: rows [32w,32w+32) x 64 cols, 3-pass bf16 hi/lo.
    // B fragments hoisted to ks scope: each warp loads W exactly ONCE
    // (was 2x through the mt loop) -> ~74KB/block less L1 traffic.
    wmma::fragment<wmma::accumulator, 16, 16, 16, float> fd[2][4];
#pragma unroll
    for (int mt = 0; mt < 2; mt++)
#pragma unroll
        for (int nt = 0; nt < 4; nt++) wmma::fill_fragment(fd[mt][nt], 0.f);

#pragma unroll
    for (int ks = 0; ks < 4; ks++) {
        wmma::fragment<wmma::matrix_b, 16, 16, 16, __nv_bfloat16, wmma::row_major> fbh[4], fbl[4];
#pragma unroll
        for (int nt = 0; nt < 4; nt++) {
            wmma::load_matrix_sync(fbh[nt], sWh + ks * 16 * 72 + nt * 16, 72);
            wmma::load_matrix_sync(fbl[nt], sWl + ks * 16 * 72 + nt * 16, 72);
        }
#pragma unroll
        for (int mt = 0; mt < 2; mt++) {
            wmma::fragment<wmma::matrix_a, 16, 16, 16, __nv_bfloat16, wmma::row_major> fah, fal;
            const int r0 = w * 32 + mt * 16;
            wmma::load_matrix_sync(fah, sAh + r0 * 72 + ks * 16, 72);
            wmma::load_matrix_sync(fal, sAl + r0 * 72 + ks * 16, 72);
#pragma unroll
            for (int nt = 0; nt < 4; nt++) {
                wmma::mma_sync(fd[mt][nt], fah, fbh[nt], fd[mt][nt]);
                wmma::mma_sync(fd[mt][nt], fah, fbl[nt], fd[mt][nt]);
                wmma::mma_sync(fd[mt][nt], fal, fbh[nt], fd[mt][nt]);
            }
        }
    }

    if (!SCATTER) {
        // Center: rows are contiguous (base+r) -> store fragments DIRECTLY to
        // global, no sD staging, no extra syncs. (base+127 <= padded range
        // handled: last block rows >= N_VOX would overrun -> guard per mt tile.)
#pragma unroll
        for (int mt = 0; mt < 2; mt++) {
            const int r0 = base + w * 32 + mt * 16;
            if (r0 + 15 < N_VOX) {
#pragma unroll
                for (int nt = 0; nt < 4; nt++)
                    wmma::store_matrix_sync(H + (size_t)r0 * 64 + nt * 16,
                                            fd[mt][nt], 64, wmma::mem_row_major);
            } else {
                // tail tile: stage via sD and guarded scalar stores
                __syncwarp();
#pragma unroll
                for (int nt = 0; nt < 4; nt++)
                    wmma::store_matrix_sync(sD + (w * 32 + mt * 16) * 64 + nt * 16,
                                            fd[mt][nt], 64, wmma::mem_row_major);
                __syncwarp();
                const int rsub = lane >> 4;
                const int c4   = lane & 15;
#pragma unroll
                for (int j = 0; j < 8; j++) {
                    const int rr = w * 32 + mt * 16 + j * 2 + rsub;
                    const int gr = base + rr;
                    if (gr < N_VOX)
                        *reinterpret_cast<float4*>(H + (size_t)gr * 64 + c4 * 4) =
                            *reinterpret_cast<const float4*>(sD + rr * 64 + c4 * 4);
                }
            }
        }
        return;
    }

    __syncthreads();   // all warps done reading sA before sD overwrites it
#pragma unroll
    for (int mt = 0; mt < 2; mt++)
#pragma unroll
        for (int nt = 0; nt < 4; nt++)
            wmma::store_matrix_sync(sD + (w * 32 + mt * 16) * 64 + nt * 16,
                                    fd[mt][nt], 64, wmma::mem_row_major);
    __syncthreads();

    // Epilogue: 16 lanes per row (coalesced 256B), red-scatter.
    {
        const int rsub = lane >> 4;
        const int c4   = lane & 15;
#pragma unroll
        for (int j = 0; j < 16; j++) {
            const int r    = w * 32 + j * 2 + rsub;
            const int orow = s_orow[r];
            if (orow < N_VOX) {
                float4 v = *reinterpret_cast<const float4*>(sD + r * 64 + c4 * 4);
                RED4(H + (size_t)orow * 64 + c4 * 4, v.x, v.y, v.z, v.w);
            }
        }
    }
}

// ---------------------------------------------------------------------------
// W prep: bf16 hi/lo split into padded [27][2][64][72]
__global__ void wprep_kernel(const float* __restrict__ W)
{
    const int o = blockIdx.x;    // 0..26
    const int t = threadIdx.x;   // 128
    for (int idx = t; idx < 4608; idx += 128) {
        const int k = idx / 72, n = idx % 72;
        float v = (n < 64) ? W[(size_t)o * 4096 + k * 64 + n] : 0.f;
        __nv_bfloat16 hi = __float2bfloat16(v);
        __nv_bfloat16 lo = __float2bfloat16(v - __bfloat162float(hi));
        g_wb[(size_t)o * 9216 + idx]        = hi;
        g_wb[(size_t)o * 9216 + 4608 + idx] = lo;
    }
}

// ---------------------------------------------------------------------------
__global__ void zero_stats_kernel() { g_stats[threadIdx.x] = 0.f; }

__global__ void stats_kernel(const float* __restrict__ h, int statoff)
{
    const int t = threadIdx.x;          // 256
    const int ch = t & 63;
    const int g  = t >> 6;              // 0..3
    float s = 0.f, sq = 0.f;
    for (int row = blockIdx.x * 4 + g; row < N_VOX; row += gridDim.x * 4) {
        float v = h[(size_t)row * 64 + ch];
        s += v; sq = fmaf(v, v, sq);
    }
    __shared__ float sh[2][4][64];
    sh[0][g][ch] = s;
    sh[1][g][ch] = sq;
    __syncthreads();
    if (t < 64) {
        float ss = sh[0][0][t] + sh[0][1][t] + sh[0][2][t] + sh[0][3][t];
        atomicAdd(&g_stats[statoff + t], ss);
    } else if (t < 128) {
        int c = t - 64;
        float qq = sh[1][0][c] + sh[1][1][c] + sh[1][2][c] + sh[1][3][c];
        atomicAdd(&g_stats[statoff + 64 + c], qq);
    }
}

__global__ void finalize_stats_kernel(const float* __restrict__ gamma,
                                      const float* __restrict__ beta,
                                      int statoff, int coefoff)
{
    const int c = threadIdx.x;  // 64
    const float inv_n = 1.0f / (float)N_VOX;
    float mu  = g_stats[statoff + c] * inv_n;
    float var = g_stats[statoff + 64 + c] * inv_n - mu * mu;
    float sc  = gamma[c] * rsqrtf(var + EPSV);
    g_coef[coefoff + c]      = sc;
    g_coef[coefoff + 64 + c] = beta[c] - mu * sc;
}

// out = relu(bn2(h2) + x)
__global__ void final_kernel(const float* __restrict__ h2,
                             const float* __restrict__ x,
                             float* __restrict__ out, int coefoff)
{
    int kk = blockIdx.x * blockDim.x + threadIdx.x;
    if (kk >= N_VOX * 16) return;
    int cb = (kk & 15) * 4;
    float4 v = reinterpret_cast<const float4*>(h2)[kk];
    float4 r = reinterpret_cast<const float4*>(x)[kk];
    float s0 = g_coef[coefoff + cb + 0], b0 = g_coef[coefoff + 64 + cb + 0];
    float s1 = g_coef[coefoff + cb + 1], b1 = g_coef[coefoff + 64 + cb + 1];
    float s2 = g_coef[coefoff + cb + 2], b2 = g_coef[coefoff + 64 + cb + 2];
    float s3 = g_coef[coefoff + cb + 3], b3 = g_coef[coefoff + 64 + cb + 3];
    v.x = fmaxf(fmaf(v.x, s0, b0) + r.x, 0.f);
    v.y = fmaxf(fmaf(v.y, s1, b1) + r.y, 0.f);
    v.z = fmaxf(fmaf(v.z, s2, b2) + r.z, 0.f);
    v.w = fmaxf(fmaf(v.w, s3, b3) + r.w, 0.f);
    reinterpret_cast<float4*>(out)[kk] = v;
}

// ---------------------------------------------------------------------------
extern "C" void kernel_launch(void* const* d_in, const int* in_sizes, int n_in,
                              void* d_out, int out_size)
{
    const float* x      = (const float*)d_in[0];
    const float* W1     = (const float*)d_in[1];
    const float* gamma1 = (const float*)d_in[2];
    const float* beta1  = (const float*)d_in[3];
    const float* W2     = (const float*)d_in[4];
    const float* gamma2 = (const float*)d_in[5];
    const float* beta2  = (const float*)d_in[6];
    const int*   in_map = (const int*)d_in[7];
    const int*   out_map= (const int*)d_in[8];
    float*       out    = (float*)d_out;

    float* h1;  cudaGetSymbolAddress((void**)&h1, g_h1);
    float* h2;  cudaGetSymbolAddress((void**)&h2, g_h2);
    __nv_bfloat16* wb;  cudaGetSymbolAddress((void**)&wb, g_wb);

    cudaFuncSetAttribute(conv_mma_kernel<true, false>,
                         cudaFuncAttributeMaxDynamicSharedMemorySize, DSMEM_BYTES);
    cudaFuncSetAttribute(conv_mma_kernel<false, false>,
                         cudaFuncAttributeMaxDynamicSharedMemorySize, DSMEM_BYTES);
    cudaFuncSetAttribute(conv_mma_kernel<true, true>,
                         cudaFuncAttributeMaxDynamicSharedMemorySize, DSMEM_BYTES);
    cudaFuncSetAttribute(conv_mma_kernel<false, true>,
                         cudaFuncAttributeMaxDynamicSharedMemorySize, DSMEM_BYTES);

    const dim3 scat_grid(PP / 128, 26);
    const int  center_blocks = (N_VOX + 127) / 128;
    const int  ew_blocks     = (N_VOX * 16 + 255) / 256;

    zero_stats_kernel<<<1, 256>>>();

    // conv1 (raw x)
    wprep_kernel<<<27, 128>>>(W1);
    conv_mma_kernel<false, false><<<center_blocks, 128, DSMEM_BYTES>>>(x, wb, nullptr, nullptr, h1);
    conv_mma_kernel<true,  false><<<scat_grid,     128, DSMEM_BYTES>>>(x, wb, in_map, out_map, h1);
    stats_kernel<<<1024, 256>>>(h1, 0);
    finalize_stats_kernel<<<1, 64>>>(gamma1, beta1, 0, 0);

    // conv2: BN1+ReLU fused into the gather (h1 stays raw)
    wprep_kernel<<<27, 128>>>(W2);
    conv_mma_kernel<false, true><<<center_blocks, 128, DSMEM_BYTES>>>(h1, wb, nullptr, nullptr, h2);
    conv_mma_kernel<true,  true><<<scat_grid,     128, DSMEM_BYTES>>>(h1, wb, in_map, out_map, h2);
    stats_kernel<<<1024, 256>>>(h2, 128);
    finalize_stats_kernel<<<1, 64>>>(gamma2, beta2, 128, 128);

    // bn2 + residual + relu -> d_out
    final_kernel<<<ew_blocks, 256>>>(h2, x, out, 128);
}

// round 8
// speedup vs baseline: 1.0398x; 1.0398x over previous
#include <cuda_runtime.h>
#include <cuda_bf16.h>
#include <mma.h>
#include <cstdint>

using namespace nvcuda;

#define N_VOX 200000
#define PP    65536
#define EPSV  1e-5f

// ---- scratch (__device__ globals; allocation-free rule) ----
__device__ float g_h1[(size_t)N_VOX * 64];
__device__ float g_h2[(size_t)N_VOX * 64];
__device__ __nv_bfloat16 g_wb[27 * 9216];  // [27][hi 64x72 | lo 64x72] bf16, padded
__device__ float g_stats[256];
__device__ float g_coef[256];  // [0:64] scale1 [64:128] shift1 [128:192] scale2 [192:256] shift2

#define RED4(p, a, b, c, d) \
    asm volatile("red.global.add.v4.f32 [%0], {%1,%2,%3,%4};" \
                 :: "l"(p), "f"(a), "f"(b), "f"(c), "f"(d) : "memory")

// smem layout (bytes):
//   [0, 36864): four 9216B WARP CHUNKS. Chunk w:
//        sAh_w bf16 [32][72]  @ +0     (4608 B)
//        sAl_w bf16 [32][72]  @ +4608  (4608 B)
//        sD_w  f32  [32][64]  @ +0     (8192 B, aliases sAh_w+sAl_w AFTER
//                                       the warp's own MMA reads; warp-private
//                                       => only __syncwarp needed)
//   [36864, 55296)  sW bf16 [hi 64x72 | lo 64x72]
//   [55296, 55808)  s_row [128]
//   [55808, 56320)  s_orow[128]
#define WCHUNK 9216
#define DSMEM_BYTES 56320

// ---------------------------------------------------------------------------
template <bool SCATTER, bool FUSE_BN>
__global__ __launch_bounds__(128, 4)
void conv_mma_kernel(const float* __restrict__ x,
                     const __nv_bfloat16* __restrict__ wb,
                     const int* __restrict__ in_map,
                     const int* __restrict__ out_map,
                     float* __restrict__ H)
{
    extern __shared__ char sm[];

    const int t    = threadIdx.x;
    const int w    = t >> 5;
    const int lane = t & 31;

    __nv_bfloat16* sAh = reinterpret_cast<__nv_bfloat16*>(sm + w * WCHUNK);
    __nv_bfloat16* sAl = sAh + 32 * 72;
    float*         sD  = reinterpret_cast<float*>(sm + w * WCHUNK);
    __nv_bfloat16* sWh = reinterpret_cast<__nv_bfloat16*>(sm + 36864);
    __nv_bfloat16* sWl = sWh + 64 * 72;
    int*           s_row  = reinterpret_cast<int*>(sm + 55296);
    int*           s_orow = s_row + 128;

    const int base = blockIdx.x * 128;
    const int ky   = SCATTER ? blockIdx.y : 0;
    const int o    = SCATTER ? (ky < 13 ? ky : ky + 1) : 13;

    if (SCATTER) {
        const size_t kbase = (size_t)ky * PP + base;
        if (__ldg(&in_map[kbase]) >= N_VOX) return;   // sentinel tail-packed tile
        s_row[t]  = __ldg(&in_map[kbase + t]);
        s_orow[t] = __ldg(&out_map[kbase + t]);
    } else {
        s_row[t] = base + t;
    }

    // Stage W_o (hi+lo, padded stride 72, 18432 B flat copy by all threads)
    {
        const uint4* src = reinterpret_cast<const uint4*>(wb + (size_t)o * 9216);
        uint4*       dst = reinterpret_cast<uint4*>(sm + 36864);
#pragma unroll
        for (int i = 0; i < 9; i++) dst[t + i * 128] = src[t + i * 128];
    }

    // Gather (+ optional fused BN1+ReLU) + bf16 hi/lo split into the WARP CHUNK.
    // 16 lanes cover one row: coalesced 2 rows / 4x128B lines per warp op.
    {
        const int rsub = lane >> 4;
        const int c4   = lane & 15;
        const float4* x4 = reinterpret_cast<const float4*>(x);
        float s0, s1, s2, s3, b0, b1, b2, b3;
        if (FUSE_BN) {
            const int cb = c4 * 4;
            s0 = g_coef[cb + 0]; b0 = g_coef[64 + cb + 0];
            s1 = g_coef[cb + 1]; b1 = g_coef[64 + cb + 1];
            s2 = g_coef[cb + 2]; b2 = g_coef[64 + cb + 2];
            s3 = g_coef[cb + 3]; b3 = g_coef[64 + cb + 3];
        }
#pragma unroll
        for (int j = 0; j < 16; j++) {
            const int rl  = j * 2 + rsub;             // local row 0..31
            const int row = s_row[w * 32 + rl];
            float4 v = make_float4(0.f, 0.f, 0.f, 0.f);
            if (row < N_VOX) v = x4[(size_t)row * 16 + c4];
            if (FUSE_BN) {
                v.x = fmaxf(fmaf(v.x, s0, b0), 0.f);
                v.y = fmaxf(fmaf(v.y, s1, b1), 0.f);
                v.z = fmaxf(fmaf(v.z, s2, b2), 0.f);
                v.w = fmaxf(fmaf(v.w, s3, b3), 0.f);
            }
            union { __nv_bfloat16 b[4]; uint2 u; } hi, lo;
            hi.b[0] = __float2bfloat16(v.x);
            hi.b[1] = __float2bfloat16(v.y);
            hi.b[2] = __float2bfloat16(v.z);
            hi.b[3] = __float2bfloat16(v.w);
            lo.b[0] = __float2bfloat16(v.x - __bfloat162float(hi.b[0]));
            lo.b[1] = __float2bfloat16(v.y - __bfloat162float(hi.b[1]));
            lo.b[2] = __float2bfloat16(v.z - __bfloat162float(hi.b[2]));
            lo.b[3] = __float2bfloat16(v.w - __bfloat162float(hi.b[3]));
            *reinterpret_cast<uint2*>(sAh + rl * 72 + c4 * 4) = hi.u;
            *reinterpret_cast<uint2*>(sAl + rl * 72 + c4 * 4) = lo.u;
        }
    }
    __syncthreads();   // the ONLY block barrier: W tile visible to all warps

    // Warp w: its 32 rows x 64 cols, 3-pass bf16 hi/lo (round-6 loop structure).
    wmma::fragment<wmma::accumulator, 16, 16, 16, float> fd[2][4];
#pragma unroll
    for (int mt = 0; mt < 2; mt++)
#pragma unroll
        for (int nt = 0; nt < 4; nt++) wmma::fill_fragment(fd[mt][nt], 0.f);

#pragma unroll
    for (int ks = 0; ks < 4; ks++) {
#pragma unroll
        for (int mt = 0; mt < 2; mt++) {
            wmma::fragment<wmma::matrix_a, 16, 16, 16, __nv_bfloat16, wmma::row_major> fah, fal;
            const int r0 = mt * 16;
            wmma::load_matrix_sync(fah, sAh + r0 * 72 + ks * 16, 72);
            wmma::load_matrix_sync(fal, sAl + r0 * 72 + ks * 16, 72);
#pragma unroll
            for (int nt = 0; nt < 4; nt++) {
                wmma::fragment<wmma::matrix_b, 16, 16, 16, __nv_bfloat16, wmma::row_major> fbh, fbl;
                wmma::load_matrix_sync(fbh, sWh + ks * 16 * 72 + nt * 16, 72);
                wmma::load_matrix_sync(fbl, sWl + ks * 16 * 72 + nt * 16, 72);
                wmma::mma_sync(fd[mt][nt], fah, fbh, fd[mt][nt]);
                wmma::mma_sync(fd[mt][nt], fah, fbl, fd[mt][nt]);
                wmma::mma_sync(fd[mt][nt], fal, fbh, fd[mt][nt]);
            }
        }
    }

    if (!SCATTER) {
        // Center: contiguous rows -> direct global fragment stores (fast path),
        // warp-private sD staging for the tail tile.
#pragma unroll
        for (int mt = 0; mt < 2; mt++) {
            const int r0 = base + w * 32 + mt * 16;
            if (r0 + 15 < N_VOX) {
#pragma unroll
                for (int nt = 0; nt < 4; nt++)
                    wmma::store_matrix_sync(H + (size_t)r0 * 64 + nt * 16,
                                            fd[mt][nt], 64, wmma::mem_row_major);
            } else {
                __syncwarp();
#pragma unroll
                for (int nt = 0; nt < 4; nt++)
                    wmma::store_matrix_sync(sD + (mt * 16) * 64 + nt * 16,
                                            fd[mt][nt], 64, wmma::mem_row_major);
                __syncwarp();
                const int rsub = lane >> 4;
                const int c4   = lane & 15;
#pragma unroll
                for (int j = 0; j < 8; j++) {
                    const int rl = mt * 16 + j * 2 + rsub;
                    const int gr = base + w * 32 + rl;
                    if (gr < N_VOX)
                        *reinterpret_cast<float4*>(H + (size_t)gr * 64 + c4 * 4) =
                            *reinterpret_cast<const float4*>(sD + rl * 64 + c4 * 4);
                }
            }
        }
        return;
    }

    // Scatter epilogue: warp-private sD (aliases this warp's own sA chunk,
    // which only this warp read) -> NO block barrier, warps de-phase freely.
    __syncwarp();
#pragma unroll
    for (int mt = 0; mt < 2; mt++)
#pragma unroll
        for (int nt = 0; nt < 4; nt++)
            wmma::store_matrix_sync(sD + (mt * 16) * 64 + nt * 16,
                                    fd[mt][nt], 64, wmma::mem_row_major);
    __syncwarp();
    {
        const int rsub = lane >> 4;
        const int c4   = lane & 15;
#pragma unroll
        for (int j = 0; j < 16; j++) {
            const int rl   = j * 2 + rsub;
            const int orow = s_orow[w * 32 + rl];
            if (orow < N_VOX) {
                float4 v = *reinterpret_cast<const float4*>(sD + rl * 64 + c4 * 4);
                RED4(H + (size_t)orow * 64 + c4 * 4, v.x, v.y, v.z, v.w);
            }
        }
    }
}

// ---------------------------------------------------------------------------
// W prep: bf16 hi/lo split into padded [27][2][64][72]
__global__ void wprep_kernel(const float* __restrict__ W)
{
    const int o = blockIdx.x;    // 0..26
    const int t = threadIdx.x;   // 128
    for (int idx = t; idx < 4608; idx += 128) {
        const int k = idx / 72, n = idx % 72;
        float v = (n < 64) ? W[(size_t)o * 4096 + k * 64 + n] : 0.f;
        __nv_bfloat16 hi = __float2bfloat16(v);
        __nv_bfloat16 lo = __float2bfloat16(v - __bfloat162float(hi));
        g_wb[(size_t)o * 9216 + idx]        = hi;
        g_wb[(size_t)o * 9216 + 4608 + idx] = lo;
    }
}

// ---------------------------------------------------------------------------
__global__ void zero_stats_kernel() { g_stats[threadIdx.x] = 0.f; }

__global__ void stats_kernel(const float* __restrict__ h, int statoff)
{
    const int t = threadIdx.x;          // 256
    const int ch = t & 63;
    const int g  = t >> 6;              // 0..3
    float s = 0.f, sq = 0.f;
#pragma unroll 4
    for (int row = blockIdx.x * 4 + g; row < N_VOX; row += gridDim.x * 4) {
        float v = h[(size_t)row * 64 + ch];
        s += v; sq = fmaf(v, v, sq);
    }
    __shared__ float sh[2][4][64];
    sh[0][g][ch] = s;
    sh[1][g][ch] = sq;
    __syncthreads();
    if (t < 64) {
        float ss = sh[0][0][t] + sh[0][1][t] + sh[0][2][t] + sh[0][3][t];
        atomicAdd(&g_stats[statoff + t], ss);
    } else if (t < 128) {
        int c = t - 64;
        float qq = sh[1][0][c] + sh[1][1][c] + sh[1][2][c] + sh[1][3][c];
        atomicAdd(&g_stats[statoff + 64 + c], qq);
    }
}

__global__ void finalize_stats_kernel(const float* __restrict__ gamma,
                                      const float* __restrict__ beta,
                                      int statoff, int coefoff)
{
    const int c = threadIdx.x;  // 64
    const float inv_n = 1.0f / (float)N_VOX;
    float mu  = g_stats[statoff + c] * inv_n;
    float var = g_stats[statoff + 64 + c] * inv_n - mu * mu;
    float sc  = gamma[c] * rsqrtf(var + EPSV);
    g_coef[coefoff + c]      = sc;
    g_coef[coefoff + 64 + c] = beta[c] - mu * sc;
}

// out = relu(bn2(h2) + x)
__global__ void final_kernel(const float* __restrict__ h2,
                             const float* __restrict__ x,
                             float* __restrict__ out, int coefoff)
{
    int kk = blockIdx.x * blockDim.x + threadIdx.x;
    if (kk >= N_VOX * 16) return;
    int cb = (kk & 15) * 4;
    float4 v = reinterpret_cast<const float4*>(h2)[kk];
    float4 r = reinterpret_cast<const float4*>(x)[kk];
    float s0 = g_coef[coefoff + cb + 0], b0 = g_coef[coefoff + 64 + cb + 0];
    float s1 = g_coef[coefoff + cb + 1], b1 = g_coef[coefoff + 64 + cb + 1];
    float s2 = g_coef[coefoff + cb + 2], b2 = g_coef[coefoff + 64 + cb + 2];
    float s3 = g_coef[coefoff + cb + 3], b3 = g_coef[coefoff + 64 + cb + 3];
    v.x = fmaxf(fmaf(v.x, s0, b0) + r.x, 0.f);
    v.y = fmaxf(fmaf(v.y, s1, b1) + r.y, 0.f);
    v.z = fmaxf(fmaf(v.z, s2, b2) + r.z, 0.f);
    v.w = fmaxf(fmaf(v.w, s3, b3) + r.w, 0.f);
    reinterpret_cast<float4*>(out)[kk] = v;
}

// ---------------------------------------------------------------------------
extern "C" void kernel_launch(void* const* d_in, const int* in_sizes, int n_in,
                              void* d_out, int out_size)
{
    const float* x      = (const float*)d_in[0];
    const float* W1     = (const float*)d_in[1];
    const float* gamma1 = (const float*)d_in[2];
    const float* beta1  = (const float*)d_in[3];
    const float* W2     = (const float*)d_in[4];
    const float* gamma2 = (const float*)d_in[5];
    const float* beta2  = (const float*)d_in[6];
    const int*   in_map = (const int*)d_in[7];
    const int*   out_map= (const int*)d_in[8];
    float*       out    = (float*)d_out;

    float* h1;  cudaGetSymbolAddress((void**)&h1, g_h1);
    float* h2;  cudaGetSymbolAddress((void**)&h2, g_h2);
    __nv_bfloat16* wb;  cudaGetSymbolAddress((void**)&wb, g_wb);

    cudaFuncSetAttribute(conv_mma_kernel<true, false>,
                         cudaFuncAttributeMaxDynamicSharedMemorySize, DSMEM_BYTES);
    cudaFuncSetAttribute(conv_mma_kernel<false, false>,
                         cudaFuncAttributeMaxDynamicSharedMemorySize, DSMEM_BYTES);
    cudaFuncSetAttribute(conv_mma_kernel<true, true>,
                         cudaFuncAttributeMaxDynamicSharedMemorySize, DSMEM_BYTES);
    cudaFuncSetAttribute(conv_mma_kernel<false, true>,
                         cudaFuncAttributeMaxDynamicSharedMemorySize, DSMEM_BYTES);

    const dim3 scat_grid(PP / 128, 26);
    const int  center_blocks = (N_VOX + 127) / 128;
    const int  ew_blocks     = (N_VOX * 16 + 255) / 256;

    zero_stats_kernel<<<1, 256>>>();

    // conv1 (raw x)
    wprep_kernel<<<27, 128>>>(W1);
    conv_mma_kernel<false, false><<<center_blocks, 128, DSMEM_BYTES>>>(x, wb, nullptr, nullptr, h1);
    conv_mma_kernel<true,  false><<<scat_grid,     128, DSMEM_BYTES>>>(x, wb, in_map, out_map, h1);
    stats_kernel<<<1024, 256>>>(h1, 0);
    finalize_stats_kernel<<<1, 64>>>(gamma1, beta1, 0, 0);

    // conv2: BN1+ReLU fused into the gather (h1 stays raw)
    wprep_kernel<<<27, 128>>>(W2);
    conv_mma_kernel<false, true><<<center_blocks, 128, DSMEM_BYTES>>>(h1, wb, nullptr, nullptr, h2);
    conv_mma_kernel<true,  true><<<scat_grid,     128, DSMEM_BYTES>>>(h1, wb, in_map, out_map, h2);
    stats_kernel<<<1024, 256>>>(h2, 128);
    finalize_stats_kernel<<<1, 64>>>(gamma2, beta2, 128, 128);

    // bn2 + residual + relu -> d_out
    final_kernel<<<ew_blocks, 256>>>(h2, x, out, 128);
}

// round 9
// speedup vs baseline: 1.2266x; 1.1797x over previous
#include <cuda_runtime.h>
#include <cuda_bf16.h>
#include <mma.h>
#include <cstdint>

using namespace nvcuda;

#define N_VOX 200000
#define PP    65536
#define EPSV  1e-5f
#define TILES 4

// ---- scratch (__device__ globals; allocation-free rule) ----
__device__ float g_h1[(size_t)N_VOX * 64];
__device__ float g_h2[(size_t)N_VOX * 64];
__device__ __nv_bfloat16 g_wb[27 * 9216];  // [27][hi 64x72 | lo 64x72] bf16, padded
__device__ float g_stats[256];
__device__ float g_coef[256];  // [0:64] scale1 [64:128] shift1 [128:192] scale2 [192:256] shift2

#define RED4(p, a, b, c, d) \
    asm volatile("red.global.add.v4.f32 [%0], {%1,%2,%3,%4};" \
                 :: "l"(p), "f"(a), "f"(b), "f"(c), "f"(d) : "memory")

// smem layout (bytes):
//   [0, 36864): four 9216B WARP CHUNKS. Chunk w:
//        sAh_w bf16 [32][72] @ +0, sAl_w bf16 [32][72] @ +4608
//        sD_w  f32  [32][64] @ +0 (aliases sA after the warp's own MMA reads;
//                                  warp-private => __syncwarp only)
//   [36864, 55296)  sW bf16 [hi 64x72 | lo 64x72]  (staged ONCE per block)
#define WCHUNK 9216
#define DSMEM_BYTES 55296

// ---------------------------------------------------------------------------
// Multi-tile conv block: processes TILES consecutive 128-pair tiles of one
// offset. W staged once; maps live in registers (shfl); no per-tile barriers.
// ---------------------------------------------------------------------------
template <bool SCATTER, bool FUSE_BN>
__global__ __launch_bounds__(128, 4)
void conv_mma_kernel(const float* __restrict__ x,
                     const __nv_bfloat16* __restrict__ wb,
                     const int* __restrict__ in_map,
                     const int* __restrict__ out_map,
                     float* __restrict__ H)
{
    extern __shared__ char sm[];

    const int t    = threadIdx.x;
    const int w    = t >> 5;
    const int lane = t & 31;

    __nv_bfloat16* sAh = reinterpret_cast<__nv_bfloat16*>(sm + w * WCHUNK);
    __nv_bfloat16* sAl = sAh + 32 * 72;
    float*         sD  = reinterpret_cast<float*>(sm + w * WCHUNK);
    __nv_bfloat16* sWh = reinterpret_cast<__nv_bfloat16*>(sm + 36864);
    __nv_bfloat16* sWl = sWh + 64 * 72;

    const int ky = SCATTER ? blockIdx.y : 0;
    const int o  = SCATTER ? (ky < 13 ? ky : ky + 1) : 13;

    // Stage W_o once per block (hi+lo, padded stride 72, 18432 B)
    {
        const uint4* src = reinterpret_cast<const uint4*>(wb + (size_t)o * 9216);
        uint4*       dst = reinterpret_cast<uint4*>(sm + 36864);
#pragma unroll
        for (int i = 0; i < 9; i++) dst[t + i * 128] = src[t + i * 128];
    }
    __syncthreads();   // the ONLY block barrier

    const int rsub = lane >> 4;       // which of 2 rows this half-warp covers
    const int c4   = lane & 15;       // float4 column within row

    float s0, s1, s2, s3, b0, b1, b2, b3;
    if (FUSE_BN) {
        const int cb = c4 * 4;
        s0 = g_coef[cb + 0]; b0 = g_coef[64 + cb + 0];
        s1 = g_coef[cb + 1]; b1 = g_coef[64 + cb + 1];
        s2 = g_coef[cb + 2]; b2 = g_coef[64 + cb + 2];
        s3 = g_coef[cb + 3]; b3 = g_coef[64 + cb + 3];
    }

    for (int tt = 0; tt < TILES; tt++) {
        const int base = (blockIdx.x * TILES + tt) * 128;
        if (!SCATTER && base >= N_VOX) break;

        // maps in registers: thread t owns pair (base + t); warp-local shfl
        int myrow, myorow;
        if (SCATTER) {
            const size_t kbase = (size_t)ky * PP + base;
            if (__ldg(&in_map[kbase]) >= N_VOX) break;  // tail-packed sentinels
            myrow  = __ldg(&in_map[kbase + t]);
            myorow = __ldg(&out_map[kbase + t]);
        }

        // ---- Gather (+ fused BN1+ReLU) + bf16 hi/lo split into warp chunk ----
        {
            const float4* x4 = reinterpret_cast<const float4*>(x);
#pragma unroll
            for (int j = 0; j < 16; j++) {
                const int rl  = j * 2 + rsub;     // local row 0..31
                const int row = SCATTER ? __shfl_sync(0xffffffffu, myrow, rl)
                                        : (base + w * 32 + rl);
                float4 v = make_float4(0.f, 0.f, 0.f, 0.f);
                if (row < N_VOX) v = x4[(size_t)row * 16 + c4];
                if (FUSE_BN) {
                    v.x = fmaxf(fmaf(v.x, s0, b0), 0.f);
                    v.y = fmaxf(fmaf(v.y, s1, b1), 0.f);
                    v.z = fmaxf(fmaf(v.z, s2, b2), 0.f);
                    v.w = fmaxf(fmaf(v.w, s3, b3), 0.f);
                }
                union { __nv_bfloat16 b[4]; uint2 u; } hi, lo;
                hi.b[0] = __float2bfloat16(v.x);
                hi.b[1] = __float2bfloat16(v.y);
                hi.b[2] = __float2bfloat16(v.z);
                hi.b[3] = __float2bfloat16(v.w);
                lo.b[0] = __float2bfloat16(v.x - __bfloat162float(hi.b[0]));
                lo.b[1] = __float2bfloat16(v.y - __bfloat162float(hi.b[1]));
                lo.b[2] = __float2bfloat16(v.z - __bfloat162float(hi.b[2]));
                lo.b[3] = __float2bfloat16(v.w - __bfloat162float(hi.b[3]));
                *reinterpret_cast<uint2*>(sAh + rl * 72 + c4 * 4) = hi.u;
                *reinterpret_cast<uint2*>(sAl + rl * 72 + c4 * 4) = lo.u;
            }
        }
        __syncwarp();

        // ---- MMA: this warp's 32 rows x 64 cols, 3-pass bf16 hi/lo ----
        wmma::fragment<wmma::accumulator, 16, 16, 16, float> fd[2][4];
#pragma unroll
        for (int mt = 0; mt < 2; mt++)
#pragma unroll
            for (int nt = 0; nt < 4; nt++) wmma::fill_fragment(fd[mt][nt], 0.f);

#pragma unroll
        for (int ks = 0; ks < 4; ks++) {
#pragma unroll
            for (int mt = 0; mt < 2; mt++) {
                wmma::fragment<wmma::matrix_a, 16, 16, 16, __nv_bfloat16, wmma::row_major> fah, fal;
                const int r0 = mt * 16;
                wmma::load_matrix_sync(fah, sAh + r0 * 72 + ks * 16, 72);
                wmma::load_matrix_sync(fal, sAl + r0 * 72 + ks * 16, 72);
#pragma unroll
                for (int nt = 0; nt < 4; nt++) {
                    wmma::fragment<wmma::matrix_b, 16, 16, 16, __nv_bfloat16, wmma::row_major> fbh, fbl;
                    wmma::load_matrix_sync(fbh, sWh + ks * 16 * 72 + nt * 16, 72);
                    wmma::load_matrix_sync(fbl, sWl + ks * 16 * 72 + nt * 16, 72);
                    wmma::mma_sync(fd[mt][nt], fah, fbh, fd[mt][nt]);
                    wmma::mma_sync(fd[mt][nt], fah, fbl, fd[mt][nt]);
                    wmma::mma_sync(fd[mt][nt], fal, fbh, fd[mt][nt]);
                }
            }
        }

        if (!SCATTER) {
            // Center: contiguous rows -> direct global fragment stores;
            // warp-private sD staging only for the tail tile.
#pragma unroll
            for (int mt = 0; mt < 2; mt++) {
                const int r0 = base + w * 32 + mt * 16;
                if (r0 + 15 < N_VOX) {
#pragma unroll
                    for (int nt = 0; nt < 4; nt++)
                        wmma::store_matrix_sync(H + (size_t)r0 * 64 + nt * 16,
                                                fd[mt][nt], 64, wmma::mem_row_major);
                } else {
                    __syncwarp();
#pragma unroll
                    for (int nt = 0; nt < 4; nt++)
                        wmma::store_matrix_sync(sD + (mt * 16) * 64 + nt * 16,
                                                fd[mt][nt], 64, wmma::mem_row_major);
                    __syncwarp();
#pragma unroll
                    for (int j = 0; j < 8; j++) {
                        const int rl = mt * 16 + j * 2 + rsub;
                        const int gr = base + w * 32 + rl;
                        if (gr < N_VOX)
                            *reinterpret_cast<float4*>(H + (size_t)gr * 64 + c4 * 4) =
                                *reinterpret_cast<const float4*>(sD + rl * 64 + c4 * 4);
                    }
                    __syncwarp();
                }
            }
            continue;
        }

        // ---- Scatter epilogue: warp-private sD, coalesced red.v4 ----
        __syncwarp();
#pragma unroll
        for (int mt = 0; mt < 2; mt++)
#pragma unroll
            for (int nt = 0; nt < 4; nt++)
                wmma::store_matrix_sync(sD + (mt * 16) * 64 + nt * 16,
                                        fd[mt][nt], 64, wmma::mem_row_major);
        __syncwarp();
#pragma unroll
        for (int j = 0; j < 16; j++) {
            const int rl   = j * 2 + rsub;
            const int orow = __shfl_sync(0xffffffffu, myorow, rl);
            if (orow < N_VOX) {
                float4 v = *reinterpret_cast<const float4*>(sD + rl * 64 + c4 * 4);
                RED4(H + (size_t)orow * 64 + c4 * 4, v.x, v.y, v.z, v.w);
            }
        }
        __syncwarp();   // sD reads done before next tile's gather overwrites
    }
}

// ---------------------------------------------------------------------------
// W prep: bf16 hi/lo split into padded [27][2][64][72]
__global__ void wprep_kernel(const float* __restrict__ W)
{
    const int o = blockIdx.x;    // 0..26
    const int t = threadIdx.x;   // 128
    for (int idx = t; idx < 4608; idx += 128) {
        const int k = idx / 72, n = idx % 72;
        float v = (n < 64) ? W[(size_t)o * 4096 + k * 64 + n] : 0.f;
        __nv_bfloat16 hi = __float2bfloat16(v);
        __nv_bfloat16 lo = __float2bfloat16(v - __bfloat162float(hi));
        g_wb[(size_t)o * 9216 + idx]        = hi;
        g_wb[(size_t)o * 9216 + 4608 + idx] = lo;
    }
}

// ---------------------------------------------------------------------------
__global__ void zero_stats_kernel() { g_stats[threadIdx.x] = 0.f; }

__global__ void stats_kernel(const float* __restrict__ h, int statoff)
{
    const int t = threadIdx.x;          // 256
    const int ch = t & 63;
    const int g  = t >> 6;              // 0..3
    float s = 0.f, sq = 0.f;
#pragma unroll 4
    for (int row = blockIdx.x * 4 + g; row < N_VOX; row += gridDim.x * 4) {
        float v = h[(size_t)row * 64 + ch];
        s += v; sq = fmaf(v, v, sq);
    }
    __shared__ float sh[2][4][64];
    sh[0][g][ch] = s;
    sh[1][g][ch] = sq;
    __syncthreads();
    if (t < 64) {
        float ss = sh[0][0][t] + sh[0][1][t] + sh[0][2][t] + sh[0][3][t];
        atomicAdd(&g_stats[statoff + t], ss);
    } else if (t < 128) {
        int c = t - 64;
        float qq = sh[1][0][c] + sh[1][1][c] + sh[1][2][c] + sh[1][3][c];
        atomicAdd(&g_stats[statoff + 64 + c], qq);
    }
}

__global__ void finalize_stats_kernel(const float* __restrict__ gamma,
                                      const float* __restrict__ beta,
                                      int statoff, int coefoff)
{
    const int c = threadIdx.x;  // 64
    const float inv_n = 1.0f / (float)N_VOX;
    float mu  = g_stats[statoff + c] * inv_n;
    float var = g_stats[statoff + 64 + c] * inv_n - mu * mu;
    float sc  = gamma[c] * rsqrtf(var + EPSV);
    g_coef[coefoff + c]      = sc;
    g_coef[coefoff + 64 + c] = beta[c] - mu * sc;
}

// out = relu(bn2(h2) + x)
__global__ void final_kernel(const float* __restrict__ h2,
                             const float* __restrict__ x,
                             float* __restrict__ out, int coefoff)
{
    int kk = blockIdx.x * blockDim.x + threadIdx.x;
    if (kk >= N_VOX * 16) return;
    int cb = (kk & 15) * 4;
    float4 v = reinterpret_cast<const float4*>(h2)[kk];
    float4 r = reinterpret_cast<const float4*>(x)[kk];
    float s0 = g_coef[coefoff + cb + 0], b0 = g_coef[coefoff + 64 + cb + 0];
    float s1 = g_coef[coefoff + cb + 1], b1 = g_coef[coefoff + 64 + cb + 1];
    float s2 = g_coef[coefoff + cb + 2], b2 = g_coef[coefoff + 64 + cb + 2];
    float s3 = g_coef[coefoff + cb + 3], b3 = g_coef[coefoff + 64 + cb + 3];
    v.x = fmaxf(fmaf(v.x, s0, b0) + r.x, 0.f);
    v.y = fmaxf(fmaf(v.y, s1, b1) + r.y, 0.f);
    v.z = fmaxf(fmaf(v.z, s2, b2) + r.z, 0.f);
    v.w = fmaxf(fmaf(v.w, s3, b3) + r.w, 0.f);
    reinterpret_cast<float4*>(out)[kk] = v;
}

// ---------------------------------------------------------------------------
extern "C" void kernel_launch(void* const* d_in, const int* in_sizes, int n_in,
                              void* d_out, int out_size)
{
    const float* x      = (const float*)d_in[0];
    const float* W1     = (const float*)d_in[1];
    const float* gamma1 = (const float*)d_in[2];
    const float* beta1  = (const float*)d_in[3];
    const float* W2     = (const float*)d_in[4];
    const float* gamma2 = (const float*)d_in[5];
    const float* beta2  = (const float*)d_in[6];
    const int*   in_map = (const int*)d_in[7];
    const int*   out_map= (const int*)d_in[8];
    float*       out    = (float*)d_out;

    float* h1;  cudaGetSymbolAddress((void**)&h1, g_h1);
    float* h2;  cudaGetSymbolAddress((void**)&h2, g_h2);
    __nv_bfloat16* wb;  cudaGetSymbolAddress((void**)&wb, g_wb);

    cudaFuncSetAttribute(conv_mma_kernel<true, false>,
                         cudaFuncAttributeMaxDynamicSharedMemorySize, DSMEM_BYTES);
    cudaFuncSetAttribute(conv_mma_kernel<false, false>,
                         cudaFuncAttributeMaxDynamicSharedMemorySize, DSMEM_BYTES);
    cudaFuncSetAttribute(conv_mma_kernel<true, true>,
                         cudaFuncAttributeMaxDynamicSharedMemorySize, DSMEM_BYTES);
    cudaFuncSetAttribute(conv_mma_kernel<false, true>,
                         cudaFuncAttributeMaxDynamicSharedMemorySize, DSMEM_BYTES);

    const dim3 scat_grid(PP / (128 * TILES), 26);
    const int  center_blocks = (N_VOX + 128 * TILES - 1) / (128 * TILES);
    const int  ew_blocks     = (N_VOX * 16 + 255) / 256;

    zero_stats_kernel<<<1, 256>>>();

    // conv1 (raw x)
    wprep_kernel<<<27, 128>>>(W1);
    conv_mma_kernel<false, false><<<center_blocks, 128, DSMEM_BYTES>>>(x, wb, nullptr, nullptr, h1);
    conv_mma_kernel<true,  false><<<scat_grid,     128, DSMEM_BYTES>>>(x, wb, in_map, out_map, h1);
    stats_kernel<<<1024, 256>>>(h1, 0);
    finalize_stats_kernel<<<1, 64>>>(gamma1, beta1, 0, 0);

    // conv2: BN1+ReLU fused into the gather (h1 stays raw)
    wprep_kernel<<<27, 128>>>(W2);
    conv_mma_kernel<false, true><<<center_blocks, 128, DSMEM_BYTES>>>(h1, wb, nullptr, nullptr, h2);
    conv_mma_kernel<true,  true><<<scat_grid,     128, DSMEM_BYTES>>>(h1, wb, in_map, out_map, h2);
    stats_kernel<<<1024, 256>>>(h2, 128);
    finalize_stats_kernel<<<1, 64>>>(gamma2, beta2, 128, 128);

    // bn2 + residual + relu -> d_out
    final_kernel<<<ew_blocks, 256>>>(h2, x, out, 128);
}

// round 10
// speedup vs baseline: 1.6446x; 1.3408x over previous
#include <cuda_runtime.h>
#include <cuda_bf16.h>
#include <cstdint>

#define N_VOX 200000
#define PP    65536
#define EPSV  1e-5f
#define TILES 4

// ---- scratch (__device__ globals; allocation-free rule) ----
__device__ float g_h1[(size_t)N_VOX * 64];
__device__ float g_h2[(size_t)N_VOX * 64];
__device__ __nv_bfloat16 g_wb[27 * 9216];  // [27][hi 64x72 | lo 64x72] bf16 row-major [k][n]
__device__ float g_stats[256];
__device__ float g_coef[256];

#define RED2(p, a, b) \
    asm volatile("red.global.add.v2.f32 [%0], {%1,%2};" \
                 :: "l"(p), "f"(a), "f"(b) : "memory")

#define LDMA4(r, addr) \
    asm volatile("ldmatrix.sync.aligned.m8n8.x4.shared.b16 {%0,%1,%2,%3}, [%4];" \
                 : "=r"((r)[0]), "=r"((r)[1]), "=r"((r)[2]), "=r"((r)[3]) : "r"(addr))

#define LDMB2T(r, addr) \
    asm volatile("ldmatrix.sync.aligned.m8n8.x2.trans.shared.b16 {%0,%1}, [%2];" \
                 : "=r"((r)[0]), "=r"((r)[1]) : "r"(addr))

#define MMA16816(d, a, b) \
    asm volatile("mma.sync.aligned.m16n8k16.row.col.f32.bf16.bf16.f32 " \
                 "{%0,%1,%2,%3},{%4,%5,%6,%7},{%8,%9},{%0,%1,%2,%3};" \
                 : "+f"((d)[0]), "+f"((d)[1]), "+f"((d)[2]), "+f"((d)[3]) \
                 : "r"((a)[0]), "r"((a)[1]), "r"((a)[2]), "r"((a)[3]), \
                   "r"((b)[0]), "r"((b)[1]))

// smem layout (bytes):
//   [0, 36864): four 9216B warp chunks: sAh bf16[32][72] @ +0, sAl @ +4608
//   [36864, 55296): sW bf16 [hi 64x72 | lo 64x72], row-major [k][n], staged once
#define WCHUNK 9216
#define DSMEM_BYTES 55296

// ---------------------------------------------------------------------------
template <bool SCATTER, bool FUSE_BN>
__global__ __launch_bounds__(128, 4)
void conv_mma_kernel(const float* __restrict__ x,
                     const __nv_bfloat16* __restrict__ wb,
                     const int* __restrict__ in_map,
                     const int* __restrict__ out_map,
                     float* __restrict__ H)
{
    extern __shared__ char sm[];

    const int t    = threadIdx.x;
    const int w    = t >> 5;
    const int lane = t & 31;

    __nv_bfloat16* sAh = reinterpret_cast<__nv_bfloat16*>(sm + w * WCHUNK);
    __nv_bfloat16* sAl = sAh + 32 * 72;

    const int ky = SCATTER ? blockIdx.y : 0;
    const int o  = SCATTER ? (ky < 13 ? ky : ky + 1) : 13;

    // Stage W_o once per block (hi+lo, stride 72 = 144B rows, 18432 B)
    {
        const uint4* src = reinterpret_cast<const uint4*>(wb + (size_t)o * 9216);
        uint4*       dst = reinterpret_cast<uint4*>(sm + 36864);
#pragma unroll
        for (int i = 0; i < 9; i++) dst[t + i * 128] = src[t + i * 128];
    }
    __syncthreads();   // only block barrier

    const uint32_t aAh = (uint32_t)__cvta_generic_to_shared(sAh);
    const uint32_t aAl = (uint32_t)__cvta_generic_to_shared(sAl);
    const uint32_t aW  = (uint32_t)__cvta_generic_to_shared(sm + 36864);

    const int rsub = lane >> 4;
    const int c4   = lane & 15;

    float s0, s1, s2, s3, b0c, b1c, b2c, b3c;
    if (FUSE_BN) {
        const int cb = c4 * 4;
        s0 = g_coef[cb + 0]; b0c = g_coef[64 + cb + 0];
        s1 = g_coef[cb + 1]; b1c = g_coef[64 + cb + 1];
        s2 = g_coef[cb + 2]; b2c = g_coef[64 + cb + 2];
        s3 = g_coef[cb + 3]; b3c = g_coef[64 + cb + 3];
    }

    for (int tt = 0; tt < TILES; tt++) {
        const int base = (blockIdx.x * TILES + tt) * 128;
        if (!SCATTER && base >= N_VOX) break;

        int myrow, myorow;
        if (SCATTER) {
            const size_t kbase = (size_t)ky * PP + base;
            if (__ldg(&in_map[kbase]) >= N_VOX) break;   // tail-packed sentinels
            myrow  = __ldg(&in_map[kbase + t]);
            myorow = __ldg(&out_map[kbase + t]);
        }

        // ---- Gather (+ fused BN1+ReLU) + bf16 hi/lo split into warp chunk ----
        {
            const float4* x4 = reinterpret_cast<const float4*>(x);
#pragma unroll
            for (int j = 0; j < 16; j++) {
                const int rl  = j * 2 + rsub;
                const int row = SCATTER ? __shfl_sync(0xffffffffu, myrow, rl)
                                        : (base + w * 32 + rl);
                float4 v = make_float4(0.f, 0.f, 0.f, 0.f);
                if (row < N_VOX) v = x4[(size_t)row * 16 + c4];
                if (FUSE_BN) {
                    v.x = fmaxf(fmaf(v.x, s0, b0c), 0.f);
                    v.y = fmaxf(fmaf(v.y, s1, b1c), 0.f);
                    v.z = fmaxf(fmaf(v.z, s2, b2c), 0.f);
                    v.w = fmaxf(fmaf(v.w, s3, b3c), 0.f);
                }
                union { __nv_bfloat16 b[4]; uint2 u; } hi, lo;
                hi.b[0] = __float2bfloat16(v.x);
                hi.b[1] = __float2bfloat16(v.y);
                hi.b[2] = __float2bfloat16(v.z);
                hi.b[3] = __float2bfloat16(v.w);
                lo.b[0] = __float2bfloat16(v.x - __bfloat162float(hi.b[0]));
                lo.b[1] = __float2bfloat16(v.y - __bfloat162float(hi.b[1]));
                lo.b[2] = __float2bfloat16(v.z - __bfloat162float(hi.b[2]));
                lo.b[3] = __float2bfloat16(v.w - __bfloat162float(hi.b[3]));
                *reinterpret_cast<uint2*>(sAh + rl * 72 + c4 * 4) = hi.u;
                *reinterpret_cast<uint2*>(sAl + rl * 72 + c4 * 4) = lo.u;
            }
        }
        __syncwarp();   // cross-lane STS -> ldmatrix visibility

        // ---- mma.sync: this warp's 32 rows x 64 cols, 3-pass bf16 hi/lo ----
        // acc: 2 mt x 8 nt x 4 f32 = 64 regs. B hoisted per ks across mt:
        // 8 nt x 2 (hi/lo) x 2 regs = 32. A = 8. Total ~110 regs, no spill.
        float acc[2][8][4];
#pragma unroll
        for (int mt = 0; mt < 2; mt++)
#pragma unroll
            for (int nt = 0; nt < 8; nt++)
#pragma unroll
                for (int i = 0; i < 4; i++) acc[mt][nt][i] = 0.f;

#pragma unroll
        for (int ks = 0; ks < 4; ks++) {
            uint32_t bh[8][2], bl[8][2];
            // B: row-major [k][n], stride 144B. ldmatrix.x2.trans:
            // lane l(0..15) -> &W[ks*16 + l][nt*8]
            const uint32_t brow = aW + (ks * 16 + (lane & 15)) * 144;
#pragma unroll
            for (int nt = 0; nt < 8; nt++) {
                LDMB2T(bh[nt], brow + nt * 16);
                LDMB2T(bl[nt], brow + nt * 16 + 9216);
            }
#pragma unroll
            for (int mt = 0; mt < 2; mt++) {
                // A: rows mt*16..+15, cols ks*16..+15; ldmatrix.x4:
                // lane l -> &A[mt*16 + l%16][ks*16 + (l/16)*8]
                const uint32_t arow = (mt * 16 + (lane & 15)) * 144
                                      + ks * 32 + ((lane >> 4) << 4);
                uint32_t ah[4], al[4];
                LDMA4(ah, aAh + arow);
                LDMA4(al, aAl + arow);
#pragma unroll
                for (int nt = 0; nt < 8; nt++) {
                    MMA16816(acc[mt][nt], ah, bh[nt]);
                    MMA16816(acc[mt][nt], ah, bl[nt]);
                    MMA16816(acc[mt][nt], al, bh[nt]);
                }
            }
        }
        __syncwarp();   // ldmatrix reads done before next tile's gather STS

        // ---- Epilogue DIRECT from acc regs (no sD smem round-trip) ----
        // acc layout m16n8: {c0,c1} -> row l/4,   cols 2(l%4)+{0,1}
        //                   {c2,c3} -> row l/4+8, cols 2(l%4)+{0,1}
        const int rq = lane >> 2;        // l/4
        const int cb = (lane & 3) * 2;
#pragma unroll
        for (int mt = 0; mt < 2; mt++) {
            const int rl1 = mt * 16 + rq;
            const int rl2 = rl1 + 8;
            int o1, o2;
            if (SCATTER) {
                o1 = __shfl_sync(0xffffffffu, myorow, rl1);
                o2 = __shfl_sync(0xffffffffu, myorow, rl2);
            } else {
                o1 = base + w * 32 + rl1;
                o2 = base + w * 32 + rl2;
            }
            if (o1 < N_VOX) {
                float* d = H + (size_t)o1 * 64 + cb;
                if (SCATTER) {
#pragma unroll
                    for (int nt = 0; nt < 8; nt++)
                        RED2(d + nt * 8, acc[mt][nt][0], acc[mt][nt][1]);
                } else {
#pragma unroll
                    for (int nt = 0; nt < 8; nt++)
                        *reinterpret_cast<float2*>(d + nt * 8) =
                            make_float2(acc[mt][nt][0], acc[mt][nt][1]);
                }
            }
            if (o2 < N_VOX) {
                float* d = H + (size_t)o2 * 64 + cb;
                if (SCATTER) {
#pragma unroll
                    for (int nt = 0; nt < 8; nt++)
                        RED2(d + nt * 8, acc[mt][nt][2], acc[mt][nt][3]);
                } else {
#pragma unroll
                    for (int nt = 0; nt < 8; nt++)
                        *reinterpret_cast<float2*>(d + nt * 8) =
                            make_float2(acc[mt][nt][2], acc[mt][nt][3]);
                }
            }
        }
    }
}

// ---------------------------------------------------------------------------
// W prep: bf16 hi/lo split into padded [27][2][64(k)][72(n)]
__global__ void wprep_kernel(const float* __restrict__ W)
{
    const int o = blockIdx.x;
    const int t = threadIdx.x;   // 128
    for (int idx = t; idx < 4608; idx += 128) {
        const int k = idx / 72, n = idx % 72;
        float v = (n < 64) ? W[(size_t)o * 4096 + k * 64 + n] : 0.f;
        __nv_bfloat16 hi = __float2bfloat16(v);
        __nv_bfloat16 lo = __float2bfloat16(v - __bfloat162float(hi));
        g_wb[(size_t)o * 9216 + idx]        = hi;
        g_wb[(size_t)o * 9216 + 4608 + idx] = lo;
    }
}

// ---------------------------------------------------------------------------
__global__ void zero_stats_kernel() { g_stats[threadIdx.x] = 0.f; }

__global__ void stats_kernel(const float* __restrict__ h, int statoff)
{
    const int t = threadIdx.x;          // 256
    const int ch = t & 63;
    const int g  = t >> 6;
    float s = 0.f, sq = 0.f;
#pragma unroll 4
    for (int row = blockIdx.x * 4 + g; row < N_VOX; row += gridDim.x * 4) {
        float v = h[(size_t)row * 64 + ch];
        s += v; sq = fmaf(v, v, sq);
    }
    __shared__ float sh[2][4][64];
    sh[0][g][ch] = s;
    sh[1][g][ch] = sq;
    __syncthreads();
    if (t < 64) {
        float ss = sh[0][0][t] + sh[0][1][t] + sh[0][2][t] + sh[0][3][t];
        atomicAdd(&g_stats[statoff + t], ss);
    } else if (t < 128) {
        int c = t - 64;
        float qq = sh[1][0][c] + sh[1][1][c] + sh[1][2][c] + sh[1][3][c];
        atomicAdd(&g_stats[statoff + 64 + c], qq);
    }
}

__global__ void finalize_stats_kernel(const float* __restrict__ gamma,
                                      const float* __restrict__ beta,
                                      int statoff, int coefoff)
{
    const int c = threadIdx.x;  // 64
    const float inv_n = 1.0f / (float)N_VOX;
    float mu  = g_stats[statoff + c] * inv_n;
    float var = g_stats[statoff + 64 + c] * inv_n - mu * mu;
    float sc  = gamma[c] * rsqrtf(var + EPSV);
    g_coef[coefoff + c]      = sc;
    g_coef[coefoff + 64 + c] = beta[c] - mu * sc;
}

// out = relu(bn2(h2) + x)
__global__ void final_kernel(const float* __restrict__ h2,
                             const float* __restrict__ x,
                             float* __restrict__ out, int coefoff)
{
    int kk = blockIdx.x * blockDim.x + threadIdx.x;
    if (kk >= N_VOX * 16) return;
    int cb = (kk & 15) * 4;
    float4 v = reinterpret_cast<const float4*>(h2)[kk];
    float4 r = reinterpret_cast<const float4*>(x)[kk];
    float s0 = g_coef[coefoff + cb + 0], b0 = g_coef[coefoff + 64 + cb + 0];
    float s1 = g_coef[coefoff + cb + 1], b1 = g_coef[coefoff + 64 + cb + 1];
    float s2 = g_coef[coefoff + cb + 2], b2 = g_coef[coefoff + 64 + cb + 2];
    float s3 = g_coef[coefoff + cb + 3], b3 = g_coef[coefoff + 64 + cb + 3];
    v.x = fmaxf(fmaf(v.x, s0, b0) + r.x, 0.f);
    v.y = fmaxf(fmaf(v.y, s1, b1) + r.y, 0.f);
    v.z = fmaxf(fmaf(v.z, s2, b2) + r.z, 0.f);
    v.w = fmaxf(fmaf(v.w, s3, b3) + r.w, 0.f);
    reinterpret_cast<float4*>(out)[kk] = v;
}

// ---------------------------------------------------------------------------
extern "C" void kernel_launch(void* const* d_in, const int* in_sizes, int n_in,
                              void* d_out, int out_size)
{
    const float* x      = (const float*)d_in[0];
    const float* W1     = (const float*)d_in[1];
    const float* gamma1 = (const float*)d_in[2];
    const float* beta1  = (const float*)d_in[3];
    const float* W2     = (const float*)d_in[4];
    const float* gamma2 = (const float*)d_in[5];
    const float* beta2  = (const float*)d_in[6];
    const int*   in_map = (const int*)d_in[7];
    const int*   out_map= (const int*)d_in[8];
    float*       out    = (float*)d_out;

    float* h1;  cudaGetSymbolAddress((void**)&h1, g_h1);
    float* h2;  cudaGetSymbolAddress((void**)&h2, g_h2);
    __nv_bfloat16* wb;  cudaGetSymbolAddress((void**)&wb, g_wb);

    cudaFuncSetAttribute(conv_mma_kernel<true, false>,
                         cudaFuncAttributeMaxDynamicSharedMemorySize, DSMEM_BYTES);
    cudaFuncSetAttribute(conv_mma_kernel<false, false>,
                         cudaFuncAttributeMaxDynamicSharedMemorySize, DSMEM_BYTES);
    cudaFuncSetAttribute(conv_mma_kernel<true, true>,
                         cudaFuncAttributeMaxDynamicSharedMemorySize, DSMEM_BYTES);
    cudaFuncSetAttribute(conv_mma_kernel<false, true>,
                         cudaFuncAttributeMaxDynamicSharedMemorySize, DSMEM_BYTES);

    const dim3 scat_grid(PP / (128 * TILES), 26);
    const int  center_blocks = (N_VOX + 128 * TILES - 1) / (128 * TILES);
    const int  ew_blocks     = (N_VOX * 16 + 255) / 256;

    zero_stats_kernel<<<1, 256>>>();

    // conv1 (raw x)
    wprep_kernel<<<27, 128>>>(W1);
    conv_mma_kernel<false, false><<<center_blocks, 128, DSMEM_BYTES>>>(x, wb, nullptr, nullptr, h1);
    conv_mma_kernel<true,  false><<<scat_grid,     128, DSMEM_BYTES>>>(x, wb, in_map, out_map, h1);
    stats_kernel<<<1024, 256>>>(h1, 0);
    finalize_stats_kernel<<<1, 64>>>(gamma1, beta1, 0, 0);

    // conv2: BN1+ReLU fused into the gather (h1 stays raw)
    wprep_kernel<<<27, 128>>>(W2);
    conv_mma_kernel<false, true><<<center_blocks, 128, DSMEM_BYTES>>>(h1, wb, nullptr, nullptr, h2);
    conv_mma_kernel<true,  true><<<scat_grid,     128, DSMEM_BYTES>>>(h1, wb, in_map, out_map, h2);
    stats_kernel<<<1024, 256>>>(h2, 128);
    finalize_stats_kernel<<<1, 64>>>(gamma2, beta2, 128, 128);

    // bn2 + residual + relu -> d_out
    final_kernel<<<ew_blocks, 256>>>(h2, x, out, 128);
}